// round 2
// baseline (speedup 1.0000x reference)
#include <cuda_runtime.h>

#define N_NODES   50000
#define N_EDGES   800000
#define F_IN      16
#define F_EDGE    8
#define H         8
#define NUM_GRAPHS 512

// ---------------- scratch (no allocations allowed) ----------------
// y1[n][o][j] = sum_i x[n][i] * We1[j][i*H+o]   (per-node factor of edge msg)
__device__ float g_y1 [N_NODES * F_EDGE * H];   // 50000*64
__device__ float g_xb1[N_NODES * H];            // sum_i x[n][i]*be1[i*H+o]
__device__ float g_agg1[N_NODES * H];           // init: root term; then +edge msgs
__device__ float g_y2 [N_NODES * F_EDGE * H];
__device__ float g_xb2[N_NODES * H];
__device__ float g_agg2[N_NODES * H];

// ---------------- kernel A: per-node precompute for layer 1 ----------------
// thread = (node n, out-channel o). 256 thr/block -> 32 nodes/block.
__global__ void node_pre1(const float* __restrict__ x,
                          const float* __restrict__ We1,
                          const float* __restrict__ be1,
                          const float* __restrict__ root1,
                          const float* __restrict__ b1,
                          int N)
{
    __shared__ float sW[F_EDGE * F_IN * H];   // 1024
    __shared__ float sbe[F_IN * H];           // 128
    __shared__ float sroot[F_IN * H];         // 128
    __shared__ float sb[H];

    for (int t = threadIdx.x; t < F_EDGE * F_IN * H; t += blockDim.x) sW[t] = We1[t];
    for (int t = threadIdx.x; t < F_IN * H; t += blockDim.x) { sbe[t] = be1[t]; sroot[t] = root1[t]; }
    if (threadIdx.x < H) sb[threadIdx.x] = b1[threadIdx.x];
    __syncthreads();

    int gt = blockIdx.x * blockDim.x + threadIdx.x;
    int n = gt >> 3;
    int o = gt & 7;
    if (n >= N) return;

    float xv[F_IN];
    const float4* xp = (const float4*)(x + (size_t)n * F_IN);
    float4 v0 = xp[0], v1 = xp[1], v2 = xp[2], v3 = xp[3];
    xv[0]=v0.x; xv[1]=v0.y; xv[2]=v0.z; xv[3]=v0.w;
    xv[4]=v1.x; xv[5]=v1.y; xv[6]=v1.z; xv[7]=v1.w;
    xv[8]=v2.x; xv[9]=v2.y; xv[10]=v2.z; xv[11]=v2.w;
    xv[12]=v3.x; xv[13]=v3.y; xv[14]=v3.z; xv[15]=v3.w;

    float* yout = g_y1 + (size_t)n * (F_EDGE * H) + o * F_EDGE;
    #pragma unroll
    for (int j = 0; j < F_EDGE; j++) {
        float acc = 0.f;
        #pragma unroll
        for (int i = 0; i < F_IN; i++) acc += xv[i] * sW[j * (F_IN * H) + i * H + o];
        yout[j] = acc;
    }

    float xb = 0.f, r = sb[o];
    #pragma unroll
    for (int i = 0; i < F_IN; i++) {
        xb += xv[i] * sbe[i * H + o];
        r  += xv[i] * sroot[i * H + o];
    }
    g_xb1[n * H + o] = xb;
    g_agg1[n * H + o] = r;
}

// ---------------- kernel B/D: edge scatter ----------------
// thread = (edge e, out-channel o). 256 thr/block -> 32 edges/block.
__global__ void edge_scatter(const float* __restrict__ ea_g,
                             const int*   __restrict__ ei,
                             const float* __restrict__ y,
                             const float* __restrict__ xb,
                             float*       __restrict__ agg,
                             int E)
{
    __shared__ float sea[32 * F_EDGE];   // 256 floats, coalesced stage of edge_attr
    int eb = blockIdx.x * 32;
    int t = threadIdx.x;
    int lin = eb * F_EDGE + t;
    if (lin < E * F_EDGE) sea[t] = ea_g[lin];
    __syncthreads();

    int le = t >> 3;
    int o  = t & 7;
    int e = eb + le;
    if (e >= E) return;

    int src = __ldg(ei + e);
    int dst = __ldg(ei + E + e);

    const float* yp = y + (size_t)src * (F_EDGE * H) + o * F_EDGE;
    float4 ya = *(const float4*)yp;
    float4 yb = *(const float4*)(yp + 4);
    const float* eap = sea + le * F_EDGE;

    float m = __ldg(xb + src * H + o);
    m += eap[0]*ya.x + eap[1]*ya.y + eap[2]*ya.z + eap[3]*ya.w
       + eap[4]*yb.x + eap[5]*yb.y + eap[6]*yb.z + eap[7]*yb.w;

    atomicAdd(&agg[dst * H + o], m);
}

// ---------------- kernel C: relu(layer1) + per-node precompute layer 2 ----------------
__global__ void node_mid(const float* __restrict__ We2,
                         const float* __restrict__ be2,
                         const float* __restrict__ root2,
                         const float* __restrict__ b2,
                         int N)
{
    __shared__ float sW[F_EDGE * H * H];   // 512
    __shared__ float sbe[H * H];           // 64
    __shared__ float sroot[H * H];         // 64
    __shared__ float sb[H];

    for (int t = threadIdx.x; t < F_EDGE * H * H; t += blockDim.x) sW[t] = We2[t];
    for (int t = threadIdx.x; t < H * H; t += blockDim.x) { sbe[t] = be2[t]; sroot[t] = root2[t]; }
    if (threadIdx.x < H) sb[threadIdx.x] = b2[threadIdx.x];
    __syncthreads();

    int gt = blockIdx.x * blockDim.x + threadIdx.x;
    int n = gt >> 3;
    int o = gt & 7;
    if (n >= N) return;

    float h[H];
    const float4* ap = (const float4*)(g_agg1 + (size_t)n * H);
    float4 a0 = ap[0], a1 = ap[1];
    h[0]=fmaxf(a0.x,0.f); h[1]=fmaxf(a0.y,0.f); h[2]=fmaxf(a0.z,0.f); h[3]=fmaxf(a0.w,0.f);
    h[4]=fmaxf(a1.x,0.f); h[5]=fmaxf(a1.y,0.f); h[6]=fmaxf(a1.z,0.f); h[7]=fmaxf(a1.w,0.f);

    float* yout = g_y2 + (size_t)n * (F_EDGE * H) + o * F_EDGE;
    #pragma unroll
    for (int j = 0; j < F_EDGE; j++) {
        float acc = 0.f;
        #pragma unroll
        for (int i = 0; i < H; i++) acc += h[i] * sW[j * (H * H) + i * H + o];
        yout[j] = acc;
    }

    float xb = 0.f, r = sb[o];
    #pragma unroll
    for (int i = 0; i < H; i++) {
        xb += h[i] * sbe[i * H + o];
        r  += h[i] * sroot[i * H + o];
    }
    g_xb2[n * H + o] = xb;
    g_agg2[n * H + o] = r;
}

// ---------------- kernel E0: init output with bias ----------------
__global__ void out_init(float* __restrict__ out, const float* __restrict__ blast, int G)
{
    int g = blockIdx.x * blockDim.x + threadIdx.x;
    if (g < G) out[g] = blast[0];
}

// ---------------- kernel E: relu(layer2) + pool + readout ----------------
__global__ void pool_out(const int* __restrict__ batch,
                         const float* __restrict__ Wlast,
                         float* __restrict__ out,
                         int N)
{
    int n = blockIdx.x * blockDim.x + threadIdx.x;
    if (n >= N) return;
    const float4* ap = (const float4*)(g_agg2 + (size_t)n * H);
    float4 a0 = ap[0], a1 = ap[1];
    float s = 0.f;
    s += fmaxf(a0.x,0.f) * __ldg(Wlast + 0);
    s += fmaxf(a0.y,0.f) * __ldg(Wlast + 1);
    s += fmaxf(a0.z,0.f) * __ldg(Wlast + 2);
    s += fmaxf(a0.w,0.f) * __ldg(Wlast + 3);
    s += fmaxf(a1.x,0.f) * __ldg(Wlast + 4);
    s += fmaxf(a1.y,0.f) * __ldg(Wlast + 5);
    s += fmaxf(a1.z,0.f) * __ldg(Wlast + 6);
    s += fmaxf(a1.w,0.f) * __ldg(Wlast + 7);
    atomicAdd(&out[__ldg(batch + n)], s);
}

// ---------------- launch ----------------
extern "C" void kernel_launch(void* const* d_in, const int* in_sizes, int n_in,
                              void* d_out, int out_size)
{
    const float* x         = (const float*)d_in[0];
    const int*   edge_index= (const int*)  d_in[1];
    const float* edge_attr = (const float*)d_in[2];
    const int*   batch     = (const int*)  d_in[3];
    const float* We1       = (const float*)d_in[4];
    const float* be1       = (const float*)d_in[5];
    const float* root1     = (const float*)d_in[6];
    const float* b1        = (const float*)d_in[7];
    const float* We2       = (const float*)d_in[8];
    const float* be2       = (const float*)d_in[9];
    const float* root2     = (const float*)d_in[10];
    const float* b2        = (const float*)d_in[11];
    const float* Wlast     = (const float*)d_in[12];
    const float* blast     = (const float*)d_in[13];
    float* out = (float*)d_out;

    int N = in_sizes[0] / F_IN;
    int E = in_sizes[1] / 2;
    int G = out_size;

    float *y1, *xb1, *agg1, *y2, *xb2, *agg2;
    cudaGetSymbolAddress((void**)&y1,  g_y1);
    cudaGetSymbolAddress((void**)&xb1, g_xb1);
    cudaGetSymbolAddress((void**)&agg1,g_agg1);
    cudaGetSymbolAddress((void**)&y2,  g_y2);
    cudaGetSymbolAddress((void**)&xb2, g_xb2);
    cudaGetSymbolAddress((void**)&agg2,g_agg2);

    dim3 blk(256);
    int node_blocks = (N * H + 255) / 256;
    int edge_blocks = (E + 31) / 32;

    node_pre1<<<node_blocks, blk>>>(x, We1, be1, root1, b1, N);
    edge_scatter<<<edge_blocks, blk>>>(edge_attr, edge_index, y1, xb1, agg1, E);
    node_mid<<<node_blocks, blk>>>(We2, be2, root2, b2, N);
    edge_scatter<<<edge_blocks, blk>>>(edge_attr, edge_index, y2, xb2, agg2, E);
    out_init<<<(G + 255) / 256, blk>>>(out, blast, G);
    pool_out<<<(N + 255) / 256, blk>>>(batch, Wlast, out, N);
}